// round 12
// baseline (speedup 1.0000x reference)
#include <cuda_runtime.h>

#define B_TOT    8192
#define T_LEN    512
#define F_IN     24
#define H_DIM    12
#define ROWS_TOTAL (B_TOT * T_LEN)
#define SCALE_T  2.885390082f   // 2*log2(e)

// ---- K1 (projection) config ----
#define K1_GRID  2048
#define K1_BLOCK 128
#define K1_ROWS  64
#define K1_ITERS (ROWS_TOTAL / (K1_GRID * K1_ROWS))   // 32
#define K1_STRIDE 28
#define K1_BUF   (K1_ROWS * K1_STRIDE)                // 1792 floats
#define K1_SMEM  (2 * K1_BUF * 4)                     // 14336 B

// ---- K2 (recurrence) config ----
#define EPB      8
#define K2_GRID  (B_TOT / EPB)                        // 1024
#define CHUNK    8
#define NCHUNK   (T_LEN / CHUNK)                      // 64

typedef unsigned long long u64;

// xp scratch, laid out [b][chunk][sub][tt][3] floats (96 floats per (b,chunk))
__device__ float g_xp[(long)ROWS_TOTAL * H_DIM];

__device__ __forceinline__ unsigned smem_u32(const void* p) {
    return (unsigned)__cvta_generic_to_shared(p);
}
__device__ __forceinline__ void cp_async16(unsigned dst, const void* src) {
    asm volatile("cp.async.cg.shared.global [%0], [%1], 16;\n" :: "r"(dst), "l"(src));
}
__device__ __forceinline__ void cp_commit() {
    asm volatile("cp.async.commit_group;\n" ::: "memory");
}
template <int N> __device__ __forceinline__ void cp_wait() {
    asm volatile("cp.async.wait_group %0;\n" :: "n"(N) : "memory");
}

__device__ __forceinline__ u64 pack2(float lo, float hi) {
    u64 d; asm("mov.b64 %0, {%1, %2};" : "=l"(d) : "f"(lo), "f"(hi)); return d;
}
__device__ __forceinline__ void unpack2(u64 d, float& lo, float& hi) {
    asm("mov.b64 {%0, %1}, %2;" : "=f"(lo), "=f"(hi) : "l"(d));
}
__device__ __forceinline__ u64 fma2(u64 a, u64 b, u64 c) {
    u64 d; asm("fma.rn.f32x2 %0, %1, %2, %3;" : "=l"(d) : "l"(a), "l"(b), "l"(c)); return d;
}
__device__ __forceinline__ u64 add2(u64 a, u64 b) {
    u64 d; asm("add.rn.f32x2 %0, %1, %2;" : "=l"(d) : "l"(a), "l"(b)); return d;
}
__device__ __forceinline__ float hadd2(u64 a) {
    float lo, hi; unpack2(a, lo, hi); return lo + hi;
}

// tanh on PRESCALED input: sx = 2*log2(e)*x  ->  tanh(x) = 1 - 2*rcp(2^sx + 1).
__device__ __forceinline__ float tanh_prescaled(float sx) {
    float e;
    asm("ex2.approx.f32 %0, %1;" : "=f"(e) : "f"(sx));
    float r;
    asm("rcp.approx.f32 %0, %1;" : "=f"(r) : "f"(e + 1.0f));
    return fmaf(-2.0f, r, 1.0f);
}

// ============================ K1: input projection ============================
__global__ void __launch_bounds__(K1_BLOCK) proj_kernel(
    const float* __restrict__ x,
    const float* __restrict__ W_ih,
    const float* __restrict__ b_ih,
    const float* __restrict__ b_hh)
{
    extern __shared__ float xsm[];   // [2][K1_ROWS][K1_STRIDE]
    const int tid = threadIdx.x;
    const int e   = tid >> 2;        // quad id (0..31)
    const int sub = tid & 3;         // 3 output rows per lane
    const int j0  = sub * 3;

    u64 wih2[3][F_IN / 2], biasp[3];
    #pragma unroll
    for (int c = 0; c < 3; c++) {
        const int j = j0 + c;
        #pragma unroll
        for (int p = 0; p < F_IN / 2; p++)
            wih2[c][p] = pack2(SCALE_T * W_ih[j * F_IN + 2 * p],
                               SCALE_T * W_ih[j * F_IN + 2 * p + 1]);
        biasp[c] = pack2(SCALE_T * (b_ih[j] + b_hh[j]), 0.0f);
    }

    const int g0 = blockIdx.x * K1_ITERS;   // row-group base (64 rows per group)
    const unsigned xsb = smem_u32(xsm);

    auto load_iter = [&](int bufi, int it) {
        const float* s = x + (long)(g0 + it) * K1_ROWS * F_IN;
        const unsigned d = xsb + (unsigned)(bufi * (K1_BUF * 4));
        #pragma unroll
        for (int j2 = 0; j2 < 3; j2++) {
            const int idx = tid * 3 + j2;          // 0..383 16B ops
            const int rr  = idx / 6;
            const int q   = idx % 6;
            cp_async16(d + (unsigned)((rr * K1_STRIDE + q * 4) * 4), s + idx * 4);
        }
        cp_commit();
    };

    load_iter(0, 0);
    for (int it = 0; it < K1_ITERS; it++) {
        __syncthreads();
        if (it + 1 < K1_ITERS) { load_iter((it + 1) & 1, it + 1); cp_wait<1>(); }
        else                   { cp_wait<0>(); }
        __syncthreads();

        const float* buf = xsm + (it & 1) * K1_BUF;
        const int R = (g0 + it) * K1_ROWS;

        #pragma unroll
        for (int half = 0; half < 2; half++) {
            const int rr = e + half * 32;
            const ulonglong2* xr = (const ulonglong2*)(buf + rr * K1_STRIDE);
            u64 a0 = biasp[0], a1 = biasp[1], a2 = biasp[2];
            #pragma unroll
            for (int q = 0; q < 6; q++) {
                ulonglong2 v = xr[q];
                a0 = fma2(wih2[0][2 * q],     v.x, a0);
                a1 = fma2(wih2[1][2 * q],     v.x, a1);
                a2 = fma2(wih2[2][2 * q],     v.x, a2);
                a0 = fma2(wih2[0][2 * q + 1], v.y, a0);
                a1 = fma2(wih2[1][2 * q + 1], v.y, a1);
                a2 = fma2(wih2[2][2 * q + 1], v.y, a2);
            }
            const int r = R + rr;  // global (b,t) row
            // layout [b][c][sub][tt][3]: (r>>3) = b*64+c ; tt = r&7
            float* dst = g_xp + (long)(r >> 3) * 96 + sub * 24 + (r & 7) * 3;
            dst[0] = hadd2(a0);
            dst[1] = hadd2(a1);
            dst[2] = hadd2(a2);
        }
    }
}

// ============================ K2: recurrence + MLP ============================
__global__ void __launch_bounds__(32) rec_kernel(
    const float* __restrict__ W_hh,
    const float* __restrict__ W1, const float* __restrict__ b1,
    const float* __restrict__ W2, const float* __restrict__ b2,
    const float* __restrict__ W3, const float* __restrict__ b3,
    float* __restrict__ out)
{
    __shared__ float sW1[144], sW2[144], sb1[12], sb2[12], sW3[12], sb3[1];
    const int tid   = threadIdx.x;
    const int e     = tid >> 2;
    const int sub   = tid & 3;
    const int j0    = sub * 3;
    const int qbase = tid & ~3;
    // reversed block order: read the xp that K1 wrote most recently first (L2)
    const int b = (gridDim.x - 1 - blockIdx.x) * EPB + e;

    for (int i = tid; i < 144; i += 32) { sW1[i] = W1[i]; sW2[i] = W2[i]; }
    if (tid < 12) { sb1[tid] = b1[tid]; sb2[tid] = b2[tid]; sW3[tid] = W3[tid]; }
    if (tid == 0) sb3[0] = b3[0];

    u64 whh2[3][6];
    #pragma unroll
    for (int c = 0; c < 3; c++) {
        const int j = j0 + c;
        #pragma unroll
        for (int p = 0; p < 6; p++)
            whh2[c][p] = pack2(SCALE_T * W_hh[j * H_DIM + 2 * p],
                               SCALE_T * W_hh[j * H_DIM + 2 * p + 1]);
    }

    // lane's xp stream: 96B contiguous per chunk
    const float* xpb = g_xp + (long)b * (NCHUNK * 96) + sub * 24;

    float xbA[24], xbB[24];
    auto loadx = [&](float (&xb)[24], int c) {
        const float4* p = (const float4*)(xpb + c * 96);
        #pragma unroll
        for (int i = 0; i < 6; i++) {
            float4 v = p[i];
            xb[4 * i + 0] = v.x; xb[4 * i + 1] = v.y;
            xb[4 * i + 2] = v.z; xb[4 * i + 3] = v.w;
        }
    };

    u64 hp[6];
    #pragma unroll
    for (int k = 0; k < 6; k++) hp[k] = 0ull;

    auto steps = [&](const float (&xc)[24]) {
        #pragma unroll
        for (int tt = 0; tt < CHUNK; tt++) {
            const float x0 = xc[3 * tt], x1 = xc[3 * tt + 1], x2 = xc[3 * tt + 2];
            u64 a0 = fma2(whh2[0][0], hp[0], pack2(x0, 0.0f));
            u64 a1 = fma2(whh2[1][0], hp[0], pack2(x1, 0.0f));
            u64 a2 = fma2(whh2[2][0], hp[0], pack2(x2, 0.0f));
            u64 t0 = fma2(whh2[0][3], hp[3], 0ull);
            u64 t1 = fma2(whh2[1][3], hp[3], 0ull);
            u64 t2 = fma2(whh2[2][3], hp[3], 0ull);
            a0 = fma2(whh2[0][1], hp[1], a0);
            a1 = fma2(whh2[1][1], hp[1], a1);
            a2 = fma2(whh2[2][1], hp[1], a2);
            t0 = fma2(whh2[0][4], hp[4], t0);
            t1 = fma2(whh2[1][4], hp[4], t1);
            t2 = fma2(whh2[2][4], hp[4], t2);
            a0 = fma2(whh2[0][2], hp[2], a0);
            a1 = fma2(whh2[1][2], hp[2], a1);
            a2 = fma2(whh2[2][2], hp[2], a2);
            t0 = fma2(whh2[0][5], hp[5], t0);
            t1 = fma2(whh2[1][5], hp[5], t1);
            t2 = fma2(whh2[2][5], hp[5], t2);

            float hl0 = tanh_prescaled(hadd2(add2(a0, t0)));
            float hl1 = tanh_prescaled(hadd2(add2(a1, t1)));
            float hl2 = tanh_prescaled(hadd2(add2(a2, t2)));

            float hs[H_DIM];
            #pragma unroll
            for (int s = 0; s < 4; s++) {
                hs[s * 3 + 0] = __shfl_sync(0xffffffffu, hl0, qbase + s);
                hs[s * 3 + 1] = __shfl_sync(0xffffffffu, hl1, qbase + s);
                hs[s * 3 + 2] = __shfl_sync(0xffffffffu, hl2, qbase + s);
            }
            #pragma unroll
            for (int p = 0; p < 6; p++) hp[p] = pack2(hs[2 * p], hs[2 * p + 1]);
        }
    };

    loadx(xbA, 0);
    #pragma unroll 1
    for (int c = 0; c < NCHUNK; c += 2) {
        loadx(xbB, c + 1);                    // prefetch odd chunk
        steps(xbA);
        if (c + 2 < NCHUNK) loadx(xbA, c + 2); // prefetch next even chunk
        steps(xbB);
    }

    __syncwarp();
    if (sub == 0) {
        float h_all[H_DIM];
        #pragma unroll
        for (int p = 0; p < 6; p++) unpack2(hp[p], h_all[2 * p], h_all[2 * p + 1]);
        float o1[H_DIM], o2[H_DIM];
        #pragma unroll
        for (int j = 0; j < H_DIM; j++) {
            float s = sb1[j];
            #pragma unroll
            for (int k = 0; k < H_DIM; k++) s = fmaf(sW1[j * H_DIM + k], h_all[k], s);
            o1[j] = fmaxf(s, 0.0f);
        }
        #pragma unroll
        for (int j = 0; j < H_DIM; j++) {
            float s = sb2[j];
            #pragma unroll
            for (int k = 0; k < H_DIM; k++) s = fmaf(sW2[j * H_DIM + k], o1[k], s);
            o2[j] = fmaxf(s, 0.0f);
        }
        float s = sb3[0];
        #pragma unroll
        for (int k = 0; k < H_DIM; k++) s = fmaf(sW3[k], o2[k], s);
        out[b] = s;
    }
}

extern "C" void kernel_launch(void* const* d_in, const int* in_sizes, int n_in,
                              void* d_out, int out_size) {
    (void)in_sizes; (void)n_in; (void)out_size;
    const float* x    = (const float*)d_in[0];
    const float* W_ih = (const float*)d_in[1];
    const float* b_ih = (const float*)d_in[2];
    const float* W_hh = (const float*)d_in[3];
    const float* b_hh = (const float*)d_in[4];
    const float* W1   = (const float*)d_in[5];
    const float* b1   = (const float*)d_in[6];
    const float* W2   = (const float*)d_in[7];
    const float* b2   = (const float*)d_in[8];
    const float* W3   = (const float*)d_in[9];
    const float* b3   = (const float*)d_in[10];
    float* out = (float*)d_out;

    proj_kernel<<<K1_GRID, K1_BLOCK, K1_SMEM>>>(x, W_ih, b_ih, b_hh);
    rec_kernel<<<K2_GRID, 32>>>(W_hh, W1, b1, W2, b2, W3, b3, out);
}

// round 14
// speedup vs baseline: 2.0733x; 2.0733x over previous
#include <cuda_runtime.h>

#define B_TOT    8192
#define T_LEN    512
#define F_IN     24
#define H_DIM    12
#define CHUNK    8
#define EPW      8            // elements per warp
#define WPB      2            // warps per block (independent; no __syncthreads)
#define EPB      (EPW * WPB)  // 16
#define NTHREADS 64
#define NCHUNK   (T_LEN / CHUNK)
#define XS_STRIDE 28          // floats per (tt,elem) x row: e*112B mod 128 all distinct
#define XWARP    (2 * CHUNK * EPW * XS_STRIDE)  // per-warp x floats (dbl buf) = 3584
#define HSTRIDE  20           // floats per elem in h buffer: e*80B mod 128 all distinct
#define HWARP    (2 * EPW * HSTRIDE)            // per-warp h floats (dbl buf) = 320
#define SMEM_BYTES ((WPB * XWARP + WPB * HWARP) * 4)   // 31232 B

typedef unsigned long long u64;

__device__ __forceinline__ unsigned smem_u32(const void* p) {
    return (unsigned)__cvta_generic_to_shared(p);
}
__device__ __forceinline__ void cp_async16(unsigned dst, const void* src) {
    asm volatile("cp.async.cg.shared.global [%0], [%1], 16;\n" :: "r"(dst), "l"(src));
}
__device__ __forceinline__ void cp_commit() {
    asm volatile("cp.async.commit_group;\n" ::: "memory");
}
template <int N> __device__ __forceinline__ void cp_wait() {
    asm volatile("cp.async.wait_group %0;\n" :: "n"(N) : "memory");
}

__device__ __forceinline__ u64 pack2(float lo, float hi) {
    u64 d; asm("mov.b64 %0, {%1, %2};" : "=l"(d) : "f"(lo), "f"(hi)); return d;
}
__device__ __forceinline__ void unpack2(u64 d, float& lo, float& hi) {
    asm("mov.b64 {%0, %1}, %2;" : "=f"(lo), "=f"(hi) : "l"(d));
}
__device__ __forceinline__ u64 fma2(u64 a, u64 b, u64 c) {
    u64 d; asm("fma.rn.f32x2 %0, %1, %2, %3;" : "=l"(d) : "l"(a), "l"(b), "l"(c)); return d;
}
__device__ __forceinline__ float hadd2(u64 a) {
    float lo, hi; unpack2(a, lo, hi); return lo + hi;
}

// ordered smem ops (asm volatile: compiler cannot reorder; LSU is in-order per warp)
__device__ __forceinline__ void sts128(unsigned addr, float a, float b, float c, float d) {
    asm volatile("st.shared.v4.f32 [%0], {%1, %2, %3, %4};"
                 :: "r"(addr), "f"(a), "f"(b), "f"(c), "f"(d) : "memory");
}
__device__ __forceinline__ float4 lds128(unsigned addr) {
    float4 v;
    asm volatile("ld.shared.v4.f32 {%0, %1, %2, %3}, [%4];"
                 : "=f"(v.x), "=f"(v.y), "=f"(v.z), "=f"(v.w) : "r"(addr) : "memory");
    return v;
}

// tanh on PRESCALED input: sx = 2*log2(e)*x -> tanh(x) = 1 - 2*rcp(2^sx + 1).
__device__ __forceinline__ float tanh_prescaled(float sx) {
    float e;
    asm("ex2.approx.f32 %0, %1;" : "=f"(e) : "f"(sx));
    float r;
    asm("rcp.approx.f32 %0, %1;" : "=f"(r) : "f"(e + 1.0f));
    return fmaf(-2.0f, r, 1.0f);
}

#define SCALE_T 2.885390082f   // 2*log2(e)

__global__ void __launch_bounds__(NTHREADS) rnn_fused_kernel(
    const float* __restrict__ x,
    const float* __restrict__ W_ih, const float* __restrict__ b_ih,
    const float* __restrict__ W_hh, const float* __restrict__ b_hh,
    const float* __restrict__ W1,   const float* __restrict__ b1,
    const float* __restrict__ W2,   const float* __restrict__ b2,
    const float* __restrict__ W3,   const float* __restrict__ b3,
    float* __restrict__ out)
{
    extern __shared__ float smemf[];
    __shared__ float sW1[144], sW2[144], sb1[12], sb2[12], sW3[12], sb3[1];

    const int tid  = threadIdx.x;
    const int wid  = tid >> 5;
    const int lane = tid & 31;
    const int e    = lane >> 2;       // element within warp (0..7)
    const int sub  = lane & 3;        // 3 h-rows per thread
    const int b    = blockIdx.x * EPB + wid * EPW + e;
    const int j0   = sub * 3;

    float* xw = smemf + wid * XWARP;                  // warp-private x staging
    float* hw = smemf + WPB * XWARP + wid * HWARP;    // warp-private h state

    // MLP weights: each warp redundantly loads all (benign duplicate writes)
    for (int i = lane; i < 144; i += 32) { sW1[i] = W1[i]; sW2[i] = W2[i]; }
    if (lane < 12) { sb1[lane] = b1[lane]; sb2[lane] = b2[lane]; sW3[lane] = W3[lane]; }
    if (lane == 0) sb3[0] = b3[0];

    // iproj weights packed (prescaled); rec weights scalar (prescaled)
    u64 wih2[3][F_IN / 2], biasp[3];
    float whh[3][H_DIM];
    #pragma unroll
    for (int c = 0; c < 3; c++) {
        const int j = j0 + c;
        #pragma unroll
        for (int p = 0; p < F_IN / 2; p++)
            wih2[c][p] = pack2(SCALE_T * W_ih[j * F_IN + 2 * p],
                               SCALE_T * W_ih[j * F_IN + 2 * p + 1]);
        #pragma unroll
        for (int k = 0; k < H_DIM; k++)
            whh[c][k] = SCALE_T * W_hh[j * H_DIM + k];
        biasp[c] = pack2(SCALE_T * (b_ih[j] + b_hh[j]), 0.0f);
    }

    // h smem addresses (byte): slot s at +s*HSTRIDE*EPW*4 within warp region
    const unsigned hbase = smem_u32(hw);
    const unsigned hrd_e = hbase + (unsigned)(e * HSTRIDE * 4);           // + slot*640
    const unsigned hwr   = hrd_e + (unsigned)(sub * 16);                  // this thread's group
    // init h=0 in slot 0
    sts128(hwr, 0.0f, 0.0f, 0.0f, 0.0f);
    __syncwarp();

    // cp.async staging: thread (e,sub) loads timesteps {sub, sub+4} of its elem
    const float* src0 = x + ((long)b * T_LEN + sub) * F_IN;
    const unsigned xwb  = smem_u32(xw);
    const unsigned dstL = xwb + (unsigned)(((sub * EPW + e) * XS_STRIDE) * 4);
    const unsigned dstH = xwb + (unsigned)((((sub + 4) * EPW + e) * XS_STRIDE) * 4);

    auto load_chunk = [&](int bufidx, int c) {
        const float* s = src0 + (long)c * (CHUNK * F_IN);
        const unsigned boff = (unsigned)bufidx * (XWARP / 2 * 4);
        #pragma unroll
        for (int q = 0; q < 6; q++) {
            cp_async16(dstL + boff + (unsigned)(q * 16), s + q * 4);
            cp_async16(dstH + boff + (unsigned)(q * 16), s + 4 * F_IN + q * 4);
        }
        cp_commit();
    };

    load_chunk(0, 0);

    for (int c = 0; c < NCHUNK; c++) {
        if (c + 1 < NCHUNK) { load_chunk((c + 1) & 1, c + 1); cp_wait<1>(); }
        else                { cp_wait<0>(); }
        __syncwarp();   // all lanes' chunk-c cp.async data visible warp-wide

        const float* buf = xw + (c & 1) * (XWARP / 2);

        #pragma unroll
        for (int tt = 0; tt < CHUNK; tt++) {
            const unsigned rds = (unsigned)((tt & 1) * (EPW * HSTRIDE * 4));
            const unsigned wrs = (unsigned)(((tt + 1) & 1) * (EPW * HSTRIDE * 4));

            // x row: 6 conflict-free LDS.128 (quad-broadcast)
            const ulonglong2* xr = (const ulonglong2*)(buf + (tt * EPW + e) * XS_STRIDE);
            u64 a0 = biasp[0], a1 = biasp[1], a2 = biasp[2];
            #pragma unroll
            for (int q = 0; q < 6; q++) {
                ulonglong2 v = xr[q];
                a0 = fma2(wih2[0][2 * q + 0], v.x, a0);
                a1 = fma2(wih2[1][2 * q + 0], v.x, a1);
                a2 = fma2(wih2[2][2 * q + 0], v.x, a2);
                a0 = fma2(wih2[0][2 * q + 1], v.y, a0);
                a1 = fma2(wih2[1][2 * q + 1], v.y, a1);
                a2 = fma2(wih2[2][2 * q + 1], v.y, a2);
            }
            const float xp0 = hadd2(a0), xp1 = hadd2(a1), xp2 = hadd2(a2);

            // h: 4 LDS.128 (groups of 3 + pad), conflict-free
            float4 h0 = lds128(hrd_e + rds);
            float4 h1 = lds128(hrd_e + rds + 16);
            float4 h2 = lds128(hrd_e + rds + 32);
            float4 h3 = lds128(hrd_e + rds + 48);

            float r0, r1, r2;
            {   // row 0: three 4-deep chains
                float u = fmaf(whh[0][0], h0.x, xp0);
                float v = whh[0][3] * h1.x;
                float w = whh[0][6] * h2.x;
                u = fmaf(whh[0][1], h0.y, u);
                v = fmaf(whh[0][4], h1.y, v);
                w = fmaf(whh[0][7], h2.y, w);
                u = fmaf(whh[0][2], h0.z, u);
                v = fmaf(whh[0][5], h1.z, v);
                w = fmaf(whh[0][8], h2.z, w);
                u = fmaf(whh[0][9], h3.x, u);
                v = fmaf(whh[0][10], h3.y, v);
                w = fmaf(whh[0][11], h3.z, w);
                r0 = (u + v) + w;
            }
            {
                float u = fmaf(whh[1][0], h0.x, xp1);
                float v = whh[1][3] * h1.x;
                float w = whh[1][6] * h2.x;
                u = fmaf(whh[1][1], h0.y, u);
                v = fmaf(whh[1][4], h1.y, v);
                w = fmaf(whh[1][7], h2.y, w);
                u = fmaf(whh[1][2], h0.z, u);
                v = fmaf(whh[1][5], h1.z, v);
                w = fmaf(whh[1][8], h2.z, w);
                u = fmaf(whh[1][9], h3.x, u);
                v = fmaf(whh[1][10], h3.y, v);
                w = fmaf(whh[1][11], h3.z, w);
                r1 = (u + v) + w;
            }
            {
                float u = fmaf(whh[2][0], h0.x, xp2);
                float v = whh[2][3] * h1.x;
                float w = whh[2][6] * h2.x;
                u = fmaf(whh[2][1], h0.y, u);
                v = fmaf(whh[2][4], h1.y, v);
                w = fmaf(whh[2][7], h2.y, w);
                u = fmaf(whh[2][2], h0.z, u);
                v = fmaf(whh[2][5], h1.z, v);
                w = fmaf(whh[2][8], h2.z, w);
                u = fmaf(whh[2][9], h3.x, u);
                v = fmaf(whh[2][10], h3.y, v);
                w = fmaf(whh[2][11], h3.z, w);
                r2 = (u + v) + w;
            }

            const float hl0 = tanh_prescaled(r0);
            const float hl1 = tanh_prescaled(r1);
            const float hl2 = tanh_prescaled(r2);

            // publish: one STS.128 (3 values + pad); no sync (lockstep + in-order LSU)
            sts128(hwr + wrs, hl0, hl1, hl2, 0.0f);
        }
    }

    __syncwarp();
    // MLP head: one thread per element; final h in slot (512 & 1) = 0
    if (sub == 0) {
        float h_all[H_DIM];
        #pragma unroll
        for (int g = 0; g < 4; g++) {
            float4 v = lds128(hrd_e + (unsigned)(g * 16));
            h_all[3 * g + 0] = v.x; h_all[3 * g + 1] = v.y; h_all[3 * g + 2] = v.z;
        }
        float o1[H_DIM], o2[H_DIM];
        #pragma unroll
        for (int j = 0; j < H_DIM; j++) {
            float s = sb1[j];
            #pragma unroll
            for (int k = 0; k < H_DIM; k++) s = fmaf(sW1[j * H_DIM + k], h_all[k], s);
            o1[j] = fmaxf(s, 0.0f);
        }
        #pragma unroll
        for (int j = 0; j < H_DIM; j++) {
            float s = sb2[j];
            #pragma unroll
            for (int k = 0; k < H_DIM; k++) s = fmaf(sW2[j * H_DIM + k], o1[k], s);
            o2[j] = fmaxf(s, 0.0f);
        }
        float s = sb3[0];
        #pragma unroll
        for (int k = 0; k < H_DIM; k++) s = fmaf(sW3[k], o2[k], s);
        out[b] = s;
    }
}

extern "C" void kernel_launch(void* const* d_in, const int* in_sizes, int n_in,
                              void* d_out, int out_size) {
    (void)in_sizes; (void)n_in; (void)out_size;
    const float* x    = (const float*)d_in[0];
    const float* W_ih = (const float*)d_in[1];
    const float* b_ih = (const float*)d_in[2];
    const float* W_hh = (const float*)d_in[3];
    const float* b_hh = (const float*)d_in[4];
    const float* W1   = (const float*)d_in[5];
    const float* b1   = (const float*)d_in[6];
    const float* W2   = (const float*)d_in[7];
    const float* b2   = (const float*)d_in[8];
    const float* W3   = (const float*)d_in[9];
    const float* b3   = (const float*)d_in[10];
    float* out = (float*)d_out;

    cudaFuncSetAttribute(rnn_fused_kernel,
                         cudaFuncAttributeMaxDynamicSharedMemorySize, SMEM_BYTES);

    dim3 grid(B_TOT / EPB);   // 512 blocks of 2 independent warps
    dim3 block(NTHREADS);     // 64 threads
    rnn_fused_kernel<<<grid, block, SMEM_BYTES>>>(
        x, W_ih, b_ih, W_hh, b_hh, W1, b1, W2, b2, W3, b3, out);
}